// round 10
// baseline (speedup 1.0000x reference)
#include <cuda_runtime.h>
#include <cstdint>

#define N_MAX 4096
#define W_MAX 128               // bitmap words per row (fixed stride)
#define NQ    (N_MAX * 4)      // row-quarter count entries
#define NB_MAX (N_MAX / 32)    // 128 sorted 32-atom blocks
#define CELLS 216              // 6x6x6 cells, size 32/6 > ... cutoff handled by AABB
#define FULLMASK 0xFFFFFFFFu

// Static scratch (allocations forbidden).
__device__ float4   g_pos4[N_MAX];     // original order {x,y,z,batch_bits}
__device__ float4   g_pos4s[N_MAX];    // cell-sorted order
__device__ int      g_perm[N_MAX];     // sorted idx -> original idx
__device__ int      g_cellid[N_MAX];
__device__ int      g_cellcnt[CELLS];
__device__ int      g_cellcur[CELLS];
__device__ float4   g_bbmin4[NB_MAX];
__device__ float4   g_bbmax4[NB_MAX];
__device__ int      g_countq[NQ];
__device__ int      g_offsetq[NQ];
__device__ unsigned g_mask[N_MAX * W_MAX];   // 2 MB bitmap, original space

__device__ __forceinline__ int warp_inc_scan(int v, int lane) {
#pragma unroll
    for (int off = 1; off < 32; off <<= 1) {
        int u = __shfl_up_sync(FULLMASK, v, off);
        if (lane >= off) v += u;
    }
    return v;
}

// ---------------------------------------------------------------------------
__global__ void reset_kernel() {
    int t = threadIdx.x;
    if (t < CELLS) g_cellcnt[t] = 0;
}

// Pack pos+batch into float4; pads get in-box pos 0 and unique sentinel batch.
// Also computes cell id and counts cell occupancy.
__global__ void pack_kernel(const float* __restrict__ pos,
                            const int* __restrict__ batch, int n, int n_pad) {
    int i = blockIdx.x * blockDim.x + threadIdx.x;
    if (i >= n_pad) return;
    float4 p;
    if (i < n) {
        p.x = pos[3 * i + 0];
        p.y = pos[3 * i + 1];
        p.z = pos[3 * i + 2];
        p.w = __int_as_float(batch[i]);
    } else {
        p = make_float4(0.f, 0.f, 0.f, __int_as_float(-2 - i));
    }
    g_pos4[i] = p;
    int cx = (int)(p.x * 0.1875f); cx = max(0, min(5, cx));
    int cy = (int)(p.y * 0.1875f); cy = max(0, min(5, cy));
    int cz = (int)(p.z * 0.1875f); cz = max(0, min(5, cz));
    int c = (cx * 6 + cy) * 6 + cz;
    g_cellid[i] = c;
    atomicAdd(&g_cellcnt[c], 1);
}

// Exclusive scan over 216 cell counts -> scatter cursors.
__global__ void cellscan_kernel() {
    __shared__ int sh[256];
    int t = threadIdx.x;
    int v = (t < CELLS) ? g_cellcnt[t] : 0;
    sh[t] = v;
    __syncthreads();
    for (int off = 1; off < 256; off <<= 1) {
        int u = (t >= off) ? sh[t - off] : 0;
        __syncthreads();
        sh[t] += u;
        __syncthreads();
    }
    if (t < CELLS) g_cellcur[t] = sh[t] - v;
}

// Scatter atoms into sorted order (rank within cell via atomics; order-free).
__global__ void scatter_kernel(int n_pad) {
    int i = blockIdx.x * blockDim.x + threadIdx.x;
    if (i >= n_pad) return;
    int r = atomicAdd(&g_cellcur[g_cellid[i]], 1);
    g_pos4s[r] = g_pos4[i];
    g_perm[r]  = i;
}

// Per-32-block AABB in sorted space (warp min/max reduce).
__global__ void aabb_kernel(int nw) {
    int b = (blockIdx.x * blockDim.x + threadIdx.x) >> 5;
    int lane = threadIdx.x & 31;
    if (b >= nw) return;
    float4 p = g_pos4s[b * 32 + lane];
    float mnx = p.x, mny = p.y, mnz = p.z;
    float mxx = p.x, mxy = p.y, mxz = p.z;
#pragma unroll
    for (int off = 16; off; off >>= 1) {
        mnx = fminf(mnx, __shfl_xor_sync(FULLMASK, mnx, off));
        mny = fminf(mny, __shfl_xor_sync(FULLMASK, mny, off));
        mnz = fminf(mnz, __shfl_xor_sync(FULLMASK, mnz, off));
        mxx = fmaxf(mxx, __shfl_xor_sync(FULLMASK, mxx, off));
        mxy = fmaxf(mxy, __shfl_xor_sync(FULLMASK, mxy, off));
        mxz = fmaxf(mxz, __shfl_xor_sync(FULLMASK, mxz, off));
    }
    if (lane == 0) {
        g_bbmin4[b] = make_float4(mnx, mny, mnz, 0.f);
        g_bbmax4[b] = make_float4(mxx, mxy, mxz, 0.f);
    }
}

// Output init (edge_index=-1, weight/vec=0) + bitmap zeroing, one kernel.
__global__ void init_kernel(float* __restrict__ out, int mp) {
    long long t = blockIdx.x * (long long)blockDim.x + threadIdx.x;
    long long out4 = (6LL * mp) >> 2;
    if (t < out4) {
        long long idx = t << 2;
        float v = (idx < 2LL * mp) ? -1.0f : 0.0f;
        *reinterpret_cast<float4*>(out + idx) = make_float4(v, v, v, v);
    } else {
        long long m = t - out4;          // zero bitmap as uint4
        if (m < (long long)(N_MAX * W_MAX / 4))
            reinterpret_cast<uint4*>(g_mask)[m] = make_uint4(0, 0, 0, 0);
    }
}

// ---------------------------------------------------------------------------
// Culled symmetric tile pass in sorted space. One warp per tile (I,J), J>=I.
// AABB gap^2 >= 25.5 -> skip tile. Surviving bits scattered into the
// ORIGINAL-space bitmap via atomicOr (order-free, deterministic content).
__global__ void mask_cull_kernel(int nw) {
    int I = blockIdx.y;
    int wslot = threadIdx.x >> 5;
    int J = blockIdx.x * 8 + wslot;
    int lane = threadIdx.x & 31;
    if (J >= nw || J < I) return;

    float4 mnI = g_bbmin4[I], mxI = g_bbmax4[I];
    float4 mnJ = g_bbmin4[J], mxJ = g_bbmax4[J];
    float gx = fmaxf(0.f, fmaxf(mnI.x - mxJ.x, mnJ.x - mxI.x));
    float gy = fmaxf(0.f, fmaxf(mnI.y - mxJ.y, mnJ.y - mxI.y));
    float gz = fmaxf(0.f, fmaxf(mnI.z - mxJ.z, mnJ.z - mxI.z));
    if (gx * gx + gy * gy + gz * gz >= 25.5f) return;   // conservative cull

    __shared__ float4 sh[8][32];
    float4 pi = g_pos4s[I * 32 + lane];
    sh[wslot][lane] = g_pos4s[J * 32 + lane];
    __syncwarp();
    int ib = __float_as_int(pi.w);

    unsigned myword = 0, tword = 0;
    if (I == J) {
#pragma unroll 8
        for (int k = 0; k < 32; k++) {
            float4 q = sh[wslot][k];
            float dx = __fadd_rn(pi.x, -q.x);
            float dy = __fadd_rn(pi.y, -q.y);
            float dz = __fadd_rn(pi.z, -q.z);
            float d2 = __fadd_rn(__fadd_rn(__fmul_rn(dx, dx), __fmul_rn(dy, dy)),
                                 __fmul_rn(dz, dz));
            bool p = (ib == __float_as_int(q.w)) & (d2 < 25.0f) & (k != lane);
            if (p) p = (__fsqrt_rn(d2) < 5.0f);
            myword |= ((unsigned)p) << k;
        }
    } else {
#pragma unroll 8
        for (int k = 0; k < 32; k++) {
            float4 q = sh[wslot][k];
            float dx = __fadd_rn(pi.x, -q.x);
            float dy = __fadd_rn(pi.y, -q.y);
            float dz = __fadd_rn(pi.z, -q.z);
            float d2 = __fadd_rn(__fadd_rn(__fmul_rn(dx, dx), __fmul_rn(dy, dy)),
                                 __fmul_rn(dz, dz));
            bool p = (ib == __float_as_int(q.w)) & (d2 < 25.0f);
            if (p) p = (__fsqrt_rn(d2) < 5.0f);
            unsigned bal = __ballot_sync(FULLMASK, p);
            myword |= ((unsigned)p) << k;
            if (lane == k) tword = bal;      // transposed: row J*32+k vs I-block
        }
    }

    // scatter to original-space bitmap
    if (myword) {
        int oi = g_perm[I * 32 + lane];
        unsigned m = myword;
        while (m) {
            int k = __ffs(m) - 1;
            m &= m - 1;
            int oj = g_perm[J * 32 + k];
            atomicOr(&g_mask[(size_t)oi * W_MAX + (oj >> 5)], 1u << (oj & 31));
        }
    }
    if (I < J && tword) {
        int oir = g_perm[J * 32 + lane];
        unsigned m = tword;
        while (m) {
            int k = __ffs(m) - 1;
            m &= m - 1;
            int oj = g_perm[I * 32 + k];
            atomicOr(&g_mask[(size_t)oir * W_MAX + (oj >> 5)], 1u << (oj & 31));
        }
    }
}

// ---------------------------------------------------------------------------
// Per (row, quarter) popcount from the bitmap. Writes (not adds) g_countq.
__global__ void countq_kernel() {
    int row  = (blockIdx.x * blockDim.x + threadIdx.x) >> 5;
    int lane = threadIdx.x & 31;
    if (row >= N_MAX) return;
    uint4 m = *reinterpret_cast<const uint4*>(g_mask + (size_t)row * W_MAX + lane * 4);
    int s = __popc(m.x) + __popc(m.y) + __popc(m.z) + __popc(m.w);
    s += __shfl_down_sync(FULLMASK, s, 4);
    s += __shfl_down_sync(FULLMASK, s, 2);
    s += __shfl_down_sync(FULLMASK, s, 1);
    if ((lane & 7) == 0) g_countq[row * 4 + (lane >> 3)] = s;
}

// Exclusive scan of 16384 quarter-counts (proven R9 code).
__global__ void scan_kernel() {
    __shared__ int wsum[32];
    int t = threadIdx.x;
    int lane = t & 31, w = t >> 5;
    int v[16];
#pragma unroll
    for (int k = 0; k < 4; k++) {
        int4 c = reinterpret_cast<int4*>(g_countq)[t * 4 + k];
        v[k * 4 + 0] = c.x; v[k * 4 + 1] = c.y;
        v[k * 4 + 2] = c.z; v[k * 4 + 3] = c.w;
    }
    int tot = 0;
    int pre[16];
#pragma unroll
    for (int k = 0; k < 16; k++) { pre[k] = tot; tot += v[k]; }
    int inc = warp_inc_scan(tot, lane);
    if (lane == 31) wsum[w] = inc;
    __syncthreads();
    if (w == 0) {
        int x = warp_inc_scan(wsum[lane], lane);
        wsum[lane] = x;
    }
    __syncthreads();
    int base = (w ? wsum[w - 1] : 0) + (inc - tot);
#pragma unroll
    for (int k = 0; k < 4; k++) {
        int4 o;
        o.x = base + pre[k * 4 + 0];
        o.y = base + pre[k * 4 + 1];
        o.z = base + pre[k * 4 + 2];
        o.w = base + pre[k * 4 + 3];
        reinterpret_cast<int4*>(g_offsetq)[t * 4 + k] = o;
    }
}

// Fill: one warp per (row, quarter) — proven R9 code (stride W_MAX).
__global__ void fill_kernel(float* __restrict__ out, int n, int mp) {
    int wid  = (blockIdx.x * blockDim.x + threadIdx.x) >> 5;
    int lane = threadIdx.x & 31;
    int row = wid >> 2;
    int q   = wid & 3;
    if (row >= n) return;
    float4 pi = g_pos4[row];
    unsigned m = g_mask[(size_t)row * W_MAX + q * 32 + lane];
    int pc = __popc(m);
    int inc = warp_inc_scan(pc, lane);
    int slot = g_offsetq[wid] + inc - pc;
    float fi = (float)row;
    int jbase = (q * 32 + lane) * 32;
    while (m) {
        int b = __ffs(m) - 1;
        m &= m - 1;
        int j = jbase + b;
        float4 pj = g_pos4[j];
        float dx = __fadd_rn(pi.x, -pj.x);
        float dy = __fadd_rn(pi.y, -pj.y);
        float dz = __fadd_rn(pi.z, -pj.z);
        float d2 = __fadd_rn(__fadd_rn(__fmul_rn(dx, dx), __fmul_rn(dy, dy)),
                             __fmul_rn(dz, dz));
        if (slot < mp) {
            out[slot]          = fi;
            out[mp + slot]     = (float)j;
            out[2 * mp + slot] = __fsqrt_rn(d2);
            float* v = out + 3 * mp + 3 * slot;
            v[0] = dx; v[1] = dy; v[2] = dz;
        }
        slot++;
    }
}

// ---------------------------------------------------------------------------
extern "C" void kernel_launch(void* const* d_in, const int* in_sizes, int n_in,
                              void* d_out, int out_size) {
    const float* pos   = (const float*)d_in[0];
    const int*   batch = (const int*)d_in[1];
    float* out = (float*)d_out;

    int n = in_sizes[1];
    if (n > N_MAX) n = N_MAX;
    int n_pad = (n + 31) & ~31;
    int nw = n_pad / 32;
    int mp = out_size / 6;

    reset_kernel<<<1, 256>>>();
    pack_kernel<<<(n_pad + 255) / 256, 256>>>(pos, batch, n, n_pad);
    cellscan_kernel<<<1, 256>>>();
    scatter_kernel<<<(n_pad + 255) / 256, 256>>>(n_pad);
    aabb_kernel<<<(nw * 32 + 255) / 256, 256>>>(nw);

    long long init_threads = (6LL * mp) / 4 + (long long)(N_MAX * W_MAX / 4);
    init_kernel<<<(int)((init_threads + 255) / 256), 256>>>(out, mp);

    dim3 mgrid((nw + 7) / 8, nw);
    mask_cull_kernel<<<mgrid, 256>>>(nw);

    countq_kernel<<<(N_MAX * 32 + 255) / 256, 256>>>();
    scan_kernel<<<1, 1024>>>();
    fill_kernel<<<(n * 4 * 32 + 255) / 256, 256>>>(out, n, mp);
}

// round 11
// speedup vs baseline: 1.3193x; 1.3193x over previous
#include <cuda_runtime.h>
#include <cstdint>

#define N_MAX 4096
#define W_MAX 128              // words per row (N_MAX/32)
#define NQ    (N_MAX * 4)     // row-quarter count entries
#define FULLMASK 0xFFFFFFFFu

// Static scratch (allocations forbidden).
__device__ float4   g_pos4[N_MAX];
__device__ int      g_countq[NQ];    // per (row, quarter) pair counts
__device__ int      g_offsetq[NQ];   // exclusive scan of g_countq
__device__ unsigned g_mask[N_MAX * W_MAX];   // 2 MB ballot bitmap, row-major words

__device__ __forceinline__ int warp_inc_scan(int v, int lane) {
#pragma unroll
    for (int off = 1; off < 32; off <<= 1) {
        int u = __shfl_up_sync(FULLMASK, v, off);
        if (lane >= off) v += u;
    }
    return v;
}

// ---------------------------------------------------------------------------
// Pack pos (N,3)+batch into float4; pad [n, n_pad) with per-row-distinct
// sentinel batch. Zeroes g_countq (graph-replay safe).
__global__ void pack_kernel(const float* __restrict__ pos,
                            const int* __restrict__ batch, int n, int n_pad) {
    int i = blockIdx.x * blockDim.x + threadIdx.x;
    if (i < N_MAX)
        reinterpret_cast<int4*>(g_countq)[i] = make_int4(0, 0, 0, 0);
    if (i < n) {
        float4 p;
        p.x = pos[3 * i + 0];
        p.y = pos[3 * i + 1];
        p.z = pos[3 * i + 2];
        p.w = __int_as_float(batch[i]);
        g_pos4[i] = p;
    } else if (i < n_pad) {
        g_pos4[i] = make_float4(1e9f, 1e9f, 1e9f, __int_as_float(-2 - i));
    }
}

// Full output init: edge_index = -1, weight/vec = 0.
__global__ void init_kernel(float* __restrict__ out, int mp) {
    long long idx = (long long)(blockIdx.x * (long long)blockDim.x + threadIdx.x) * 4;
    if (idx < 6LL * mp) {
        float v = (idx < 2LL * mp) ? -1.0f : 0.0f;
        *reinterpret_cast<float4*>(out + idx) = make_float4(v, v, v, v);
    }
}

// ---------------------------------------------------------------------------
// Pass A: symmetric 32x32 tile evaluation + fused per-quarter counting.
// One warp per tile (I,J), J>=I. Lane l owns row i=I*32+l. Step k evaluates
// column j=J*32+k. Local word = row block; ballot = transposed block.
__global__ void mask_block_kernel(int nw) {
    int I = blockIdx.y;
    int wslot = threadIdx.x >> 5;
    int J = blockIdx.x * 8 + wslot;
    int lane = threadIdx.x & 31;
    if (J >= nw || J < I) return;

    __shared__ float4 sh[8][32];
    float4 pi = g_pos4[I * 32 + lane];
    sh[wslot][lane] = g_pos4[J * 32 + lane];
    __syncwarp();
    int ib = __float_as_int(pi.w);

    unsigned myword = 0;
    if (I == J) {
#pragma unroll 8
        for (int k = 0; k < 32; k++) {
            float4 q = sh[wslot][k];
            float dx = __fadd_rn(pi.x, -q.x);
            float dy = __fadd_rn(pi.y, -q.y);
            float dz = __fadd_rn(pi.z, -q.z);
            float d2 = __fadd_rn(__fadd_rn(__fmul_rn(dx, dx), __fmul_rn(dy, dy)),
                                 __fmul_rn(dz, dz));
            bool p = (ib == __float_as_int(q.w)) & (d2 < 25.0f) & (k != lane);
            if (p) p = (__fsqrt_rn(d2) < 5.0f);
            myword |= ((unsigned)p) << k;
        }
        g_mask[(size_t)(I * 32 + lane) * nw + J] = myword;
        int pc = __popc(myword);
        if (pc) atomicAdd(&g_countq[(I * 32 + lane) * 4 + (J >> 5)], pc);
    } else {
        unsigned tword = 0;
#pragma unroll 8
        for (int k = 0; k < 32; k++) {
            float4 q = sh[wslot][k];
            float dx = __fadd_rn(pi.x, -q.x);
            float dy = __fadd_rn(pi.y, -q.y);
            float dz = __fadd_rn(pi.z, -q.z);
            float d2 = __fadd_rn(__fadd_rn(__fmul_rn(dx, dx), __fmul_rn(dy, dy)),
                                 __fmul_rn(dz, dz));
            bool p = (ib == __float_as_int(q.w)) & (d2 < 25.0f);
            if (p) p = (__fsqrt_rn(d2) < 5.0f);
            unsigned bal = __ballot_sync(FULLMASK, p);   // bit m = pred(I*32+m, j)
            myword |= ((unsigned)p) << k;
            if (lane == k) tword = bal;                  // row J*32+k, word I
        }
        g_mask[(size_t)(I * 32 + lane) * nw + J] = myword;
        g_mask[(size_t)(J * 32 + lane) * nw + I] = tword;
        int pc0 = __popc(myword);
        int pc1 = __popc(tword);
        if (pc0) atomicAdd(&g_countq[(I * 32 + lane) * 4 + (J >> 5)], pc0);
        if (pc1) atomicAdd(&g_countq[(J * 32 + lane) * 4 + (I >> 5)], pc1);
    }
}

// ---------------------------------------------------------------------------
// Exclusive scan of 16384 quarter-counts: 1024 threads x 16 (shfl, 2 barriers).
__global__ void scan_kernel() {
    __shared__ int wsum[32];
    int t = threadIdx.x;
    int lane = t & 31, w = t >> 5;
    int v[16];
#pragma unroll
    for (int k = 0; k < 4; k++) {
        int4 c = reinterpret_cast<int4*>(g_countq)[t * 4 + k];
        v[k * 4 + 0] = c.x; v[k * 4 + 1] = c.y;
        v[k * 4 + 2] = c.z; v[k * 4 + 3] = c.w;
    }
    int tot = 0;
    int pre[16];
#pragma unroll
    for (int k = 0; k < 16; k++) { pre[k] = tot; tot += v[k]; }
    int inc = warp_inc_scan(tot, lane);
    if (lane == 31) wsum[w] = inc;
    __syncthreads();
    if (w == 0) {
        int x = warp_inc_scan(wsum[lane], lane);
        wsum[lane] = x;
    }
    __syncthreads();
    int base = (w ? wsum[w - 1] : 0) + (inc - tot);
#pragma unroll
    for (int k = 0; k < 4; k++) {
        int4 o;
        o.x = base + pre[k * 4 + 0];
        o.y = base + pre[k * 4 + 1];
        o.z = base + pre[k * 4 + 2];
        o.w = base + pre[k * 4 + 3];
        reinterpret_cast<int4*>(g_offsetq)[t * 4 + k] = o;
    }
}

// ---------------------------------------------------------------------------
// Pass B: smem-staged coalesced fill. One warp per (row, quarter).
// Phase 1: expand set bits into a shared j-list (warp-local slot order).
// Phase 2: emit entries cooperatively -> all 4 output regions written as
// contiguous warp spans (full coalescing; no 4B-scatter sector blowup).
__global__ void fill_kernel(float* __restrict__ out, int n, int mp, int nw) {
    __shared__ int sj[8][1024];                 // 32 KB: max 1024 bits/quarter
    int wslot = threadIdx.x >> 5;
    int wid  = (blockIdx.x * blockDim.x + threadIdx.x) >> 5;
    int lane = threadIdx.x & 31;
    int row = wid >> 2;
    int q   = wid & 3;
    if (row >= n) return;

    unsigned m = g_mask[(size_t)row * nw + q * 32 + lane];
    int pc = __popc(m);
    int inc = warp_inc_scan(pc, lane);
    int T = __shfl_sync(FULLMASK, inc, 31);
    int pos = inc - pc;
    int jbase = (q * 32 + lane) * 32;
    while (m) {
        int b = __ffs(m) - 1;
        m &= m - 1;
        sj[wslot][pos++] = jbase + b;
    }
    __syncwarp();

    float4 pi = g_pos4[row];
    int base = g_offsetq[wid];
    float fi = (float)row;
    for (int t = lane; t < T; t += 32) {
        int j = sj[wslot][t];
        float4 pj = g_pos4[j];
        float dx = __fadd_rn(pi.x, -pj.x);
        float dy = __fadd_rn(pi.y, -pj.y);
        float dz = __fadd_rn(pi.z, -pj.z);
        float d2 = __fadd_rn(__fadd_rn(__fmul_rn(dx, dx), __fmul_rn(dy, dy)),
                             __fmul_rn(dz, dz));
        int slot = base + t;
        if (slot < mp) {
            out[slot]          = fi;             // coalesced across lanes
            out[mp + slot]     = (float)j;       // coalesced
            out[2 * mp + slot] = __fsqrt_rn(d2); // coalesced
            float* v = out + 3 * mp + 3 * slot;  // contiguous warp span
            v[0] = dx; v[1] = dy; v[2] = dz;
        }
    }
}

// ---------------------------------------------------------------------------
extern "C" void kernel_launch(void* const* d_in, const int* in_sizes, int n_in,
                              void* d_out, int out_size) {
    const float* pos   = (const float*)d_in[0];
    const int*   batch = (const int*)d_in[1];
    float* out = (float*)d_out;

    int n = in_sizes[1];
    if (n > N_MAX) n = N_MAX;
    int n_pad = (n + 31) & ~31;
    int nw = n_pad / 32;
    int mp = out_size / 6;

    pack_kernel<<<(N_MAX + 255) / 256, 256>>>(pos, batch, n, n_pad);

    long long vec4 = (6LL * mp) / 4;
    init_kernel<<<(int)((vec4 + 255) / 256), 256>>>(out, mp);

    dim3 mgrid((nw + 7) / 8, nw);
    mask_block_kernel<<<mgrid, 256>>>(nw);

    scan_kernel<<<1, 1024>>>();

    fill_kernel<<<(n * 4 * 32 + 255) / 256, 256>>>(out, n, mp, nw);
}